// round 6
// baseline (speedup 1.0000x reference)
#include <cuda_runtime.h>
#include <cstdint>

// Problem constants (fixed shapes per reference)
constexpr int B_ = 8;
constexpr int S_ = 4096;
constexpr int D_ = 2048;
constexpr int R_ = 4;
// Effective math: out[b,s,:] = relu(0.25 * (x[b,s,:] @ Bc_b) @ Ac_b),
// Bc_b = concat(adapter_b[4b..4b+3]) -> [2048,16], Ac_b -> [16,2048].

// ---- Stage 1 config ----
constexpr int KSPLIT = 8;
constexpr int KRANGE = D_ / KSPLIT;   // 256 k per block
constexpr int S1_THREADS = 256;
constexpr int S1_ROWS = 512;          // 2 rows per thread

// ---- Stage 2 config ----
constexpr int SROWS = 64;
constexpr int S2_THREADS = 256;       // each thread owns 4 d; block covers 1024 d

// Partial h: [split][row][16] -> 16 MB (L2-resident)
constexpr size_t HP_STRIDE = (size_t)B_ * S_ * 16;  // floats per split
__device__ float g_hp[KSPLIT * HP_STRIDE];

// ---- packed f32x2 helpers (sm_100+ PTX) ----
__device__ __forceinline__ unsigned long long fma2(unsigned long long a,
                                                   unsigned long long b,
                                                   unsigned long long c) {
    unsigned long long d;
    asm("fma.rn.f32x2 %0, %1, %2, %3;" : "=l"(d) : "l"(a), "l"(b), "l"(c));
    return d;
}
__device__ __forceinline__ unsigned long long add2(unsigned long long a,
                                                   unsigned long long b) {
    unsigned long long d;
    asm("add.rn.f32x2 %0, %1, %2;" : "=l"(d) : "l"(a), "l"(b));
    return d;
}
__device__ __forceinline__ unsigned long long pack2(float lo, float hi) {
    unsigned long long d;
    asm("mov.b64 %0, {%1, %2};" : "=l"(d) : "f"(lo), "f"(hi));
    return d;
}
__device__ __forceinline__ float2 unpack2(unsigned long long v) {
    float2 r;
    asm("mov.b64 {%0, %1}, %2;" : "=f"(r.x), "=f"(r.y) : "l"(v));
    return r;
}

// ============================================================================
// Stage 1: h_partial[split][row][c] = sum_{k in split range} x[row][k]*Bc[k][c]
// 256 threads, 2 rows/thread (rows tid and tid+256), 16 cols each.
// Whole B k-range (256x16 = 16KB) preloaded to smem once; x streamed from
// gmem in registers. 3 blocks/SM resident -> 24 warps/SM.
// ============================================================================
__global__ __launch_bounds__(S1_THREADS, 3) void lora_stage1(
    const float* __restrict__ x, const float* __restrict__ ab) {
    __shared__ float bs[KRANGE][16];  // 16 KB

    const int tid = threadIdx.x;
    const int row0 = blockIdx.x * S1_ROWS;
    const int split = blockIdx.y;
    const int kbase = split * KRANGE;
    const int b = row0 / S_;

    // Preload B tile: bs[k][j*4+r] = adapter_b[4b+j][kbase+k][r]
    const float* bbase = ab + (size_t)(4 * b) * D_ * R_;
#pragma unroll
    for (int t = tid; t < KRANGE * 4; t += S1_THREADS) {
        const int j = t >> 8;   // t / KRANGE
        const int k = t & 255;  // t % KRANGE -> coalesced
        float4 v = *(const float4*)(bbase + (size_t)j * (D_ * R_) +
                                    (size_t)(kbase + k) * R_);
        *(float4*)&bs[k][j * 4] = v;
    }
    __syncthreads();

    const float* xr0 = x + (size_t)(row0 + tid) * D_ + kbase;
    const float* xr1 = xr0 + (size_t)S1_THREADS * D_;

    unsigned long long acc0[8], acc1[8];
#pragma unroll
    for (int c = 0; c < 8; c++) { acc0[c] = 0ull; acc1[c] = 0ull; }

    // Process 8 k per iteration; prefetch next 8 k.
    float4 xa0 = *(const float4*)(xr0 + 0);
    float4 xa1 = *(const float4*)(xr0 + 4);
    float4 xb0 = *(const float4*)(xr1 + 0);
    float4 xb1 = *(const float4*)(xr1 + 4);

    for (int k0 = 0; k0 < KRANGE; k0 += 8) {
        const int kn = (k0 + 8 < KRANGE) ? (k0 + 8) : k0;  // harmless reload
        float4 na0 = *(const float4*)(xr0 + kn + 0);
        float4 na1 = *(const float4*)(xr0 + kn + 4);
        float4 nb0 = *(const float4*)(xr1 + kn + 0);
        float4 nb1 = *(const float4*)(xr1 + kn + 4);

        float xav[8] = {xa0.x, xa0.y, xa0.z, xa0.w, xa1.x, xa1.y, xa1.z, xa1.w};
        float xbv[8] = {xb0.x, xb0.y, xb0.z, xb0.w, xb1.x, xb1.y, xb1.z, xb1.w};

#pragma unroll
        for (int kk = 0; kk < 8; kk++) {
            const unsigned long long x0 = pack2(xav[kk], xav[kk]);
            const unsigned long long x1 = pack2(xbv[kk], xbv[kk]);
            const ulonglong2* brow = (const ulonglong2*)&bs[k0 + kk][0];
            ulonglong2 bp0 = brow[0];
            ulonglong2 bp1 = brow[1];
            ulonglong2 bp2 = brow[2];
            ulonglong2 bp3 = brow[3];
            acc0[0] = fma2(x0, bp0.x, acc0[0]);
            acc0[1] = fma2(x0, bp0.y, acc0[1]);
            acc0[2] = fma2(x0, bp1.x, acc0[2]);
            acc0[3] = fma2(x0, bp1.y, acc0[3]);
            acc0[4] = fma2(x0, bp2.x, acc0[4]);
            acc0[5] = fma2(x0, bp2.y, acc0[5]);
            acc0[6] = fma2(x0, bp3.x, acc0[6]);
            acc0[7] = fma2(x0, bp3.y, acc0[7]);
            acc1[0] = fma2(x1, bp0.x, acc1[0]);
            acc1[1] = fma2(x1, bp0.y, acc1[1]);
            acc1[2] = fma2(x1, bp1.x, acc1[2]);
            acc1[3] = fma2(x1, bp1.y, acc1[3]);
            acc1[4] = fma2(x1, bp2.x, acc1[4]);
            acc1[5] = fma2(x1, bp2.y, acc1[5]);
            acc1[6] = fma2(x1, bp3.x, acc1[6]);
            acc1[7] = fma2(x1, bp3.y, acc1[7]);
        }
        xa0 = na0; xa1 = na1; xb0 = nb0; xb1 = nb1;
    }

    // Write partial h rows (16 floats each) as 2x STG.128 per row
    float* hp = g_hp + (size_t)split * HP_STRIDE;
    float* o0 = hp + (size_t)(row0 + tid) * 16;
    float* o1 = hp + (size_t)(row0 + tid + S1_THREADS) * 16;
    ((ulonglong2*)o0)[0] = make_ulonglong2(acc0[0], acc0[1]);
    ((ulonglong2*)o0)[1] = make_ulonglong2(acc0[2], acc0[3]);
    ((ulonglong2*)o0)[2] = make_ulonglong2(acc0[4], acc0[5]);
    ((ulonglong2*)o0)[3] = make_ulonglong2(acc0[6], acc0[7]);
    ((ulonglong2*)o1)[0] = make_ulonglong2(acc1[0], acc1[1]);
    ((ulonglong2*)o1)[1] = make_ulonglong2(acc1[2], acc1[3]);
    ((ulonglong2*)o1)[2] = make_ulonglong2(acc1[4], acc1[5]);
    ((ulonglong2*)o1)[3] = make_ulonglong2(acc1[6], acc1[7]);
}

// ============================================================================
// Stage 2: out[row][d] = relu( 0.25 * sum_c h[row][c] * Ac[c][d] )
// 256 threads, each owns 4 consecutive d (A slice in regs); block covers
// 1024 d x 64 rows. hs filled FIRST (before areg is live) to keep register
// pressure <= 85 for 3 blocks/SM.
// ============================================================================
__global__ __launch_bounds__(S2_THREADS, 3) void lora_stage2(
    const float* __restrict__ aa, float* __restrict__ out) {
    __shared__ float2 hs[SROWS][16];  // duplicated (0.25*h, 0.25*h) pairs, 8KB

    const int tid = threadIdx.x;
    const int b = blockIdx.z;
    const int s0 = blockIdx.x * SROWS;
    const size_t row0 = (size_t)b * S_ + s0;
    const int d0 = blockIdx.y * 1024 + tid * 4;

    // Fill hs FIRST: sum 8 partials, scale 0.25, duplicate into pairs.
    {
        const float2* hp = (const float2*)(g_hp) + row0 * 8;
#pragma unroll
        for (int g = 0; g < (SROWS * 8) / S2_THREADS; g++) {
            const int i = tid + g * S2_THREADS;
            float a = 0.0f, c2 = 0.0f;
#pragma unroll
            for (int s = 0; s < KSPLIT; s++) {
                float2 v = hp[(size_t)s * (HP_STRIDE / 2) + i];
                a += v.x;
                c2 += v.y;
            }
            a *= 0.25f;
            c2 *= 0.25f;
            const int rr = i >> 3;
            const int cp = i & 7;
            hs[rr][2 * cp + 0] = make_float2(a, a);
            hs[rr][2 * cp + 1] = make_float2(c2, c2);
        }
    }
    __syncthreads();

    // A slice into registers: 16 c x 4 d -> 16 x 2 f32x2
    unsigned long long areg[16][2];
#pragma unroll
    for (int j = 0; j < 4; j++) {
#pragma unroll
        for (int r = 0; r < 4; r++) {
            float4 v = *(const float4*)(aa + (size_t)(4 * b + j) * (R_ * D_) +
                                        (size_t)r * D_ + d0);
            areg[j * 4 + r][0] = pack2(v.x, v.y);
            areg[j * 4 + r][1] = pack2(v.z, v.w);
        }
    }

    float* orow = out + row0 * D_ + d0;
    for (int rr = 0; rr < SROWS; rr++) {
        unsigned long long a0 = 0ull, a1 = 0ull, a2 = 0ull, a3 = 0ull;
#pragma unroll
        for (int c = 0; c < 16; c += 2) {
            ulonglong2 hv = *(const ulonglong2*)&hs[rr][c];
            a0 = fma2(hv.x, areg[c + 0][0], a0);
            a1 = fma2(hv.x, areg[c + 0][1], a1);
            a2 = fma2(hv.y, areg[c + 1][0], a2);
            a3 = fma2(hv.y, areg[c + 1][1], a3);
        }
        const unsigned long long s01 = add2(a0, a2);
        const unsigned long long s23 = add2(a1, a3);
        float2 v0 = unpack2(s01);
        float2 v1 = unpack2(s23);
        float4 o;
        o.x = fmaxf(v0.x, 0.0f);
        o.y = fmaxf(v0.y, 0.0f);
        o.z = fmaxf(v1.x, 0.0f);
        o.w = fmaxf(v1.y, 0.0f);
        *(float4*)(orow + (size_t)rr * D_) = o;
    }
}

extern "C" void kernel_launch(void* const* d_in, const int* in_sizes, int n_in,
                              void* d_out, int out_size) {
    const float* x = (const float*)d_in[0];
    const float* ab = (const float*)d_in[1];
    const float* aa = (const float*)d_in[2];
    float* out = (float*)d_out;

    dim3 g1((B_ * S_) / S1_ROWS, KSPLIT);  // (64, 8) = 512 blocks
    lora_stage1<<<g1, S1_THREADS>>>(x, ab);

    dim3 g2(S_ / SROWS, D_ / (S2_THREADS * 4), B_);  // (64, 2, 8) = 1024 blocks
    lora_stage2<<<g2, S2_THREADS>>>(aa, out);
}

// round 7
// speedup vs baseline: 1.0022x; 1.0022x over previous
#include <cuda_runtime.h>
#include <cstdint>

// Problem constants (fixed shapes per reference)
constexpr int B_ = 8;
constexpr int S_ = 4096;
constexpr int D_ = 2048;
constexpr int R_ = 4;
// Effective math: out[b,s,:] = relu(0.25 * (x[b,s,:] @ Bc_b) @ Ac_b),
// Bc_b = concat(adapter_b[4b..4b+3]) -> [2048,16], Ac_b -> [16,2048].

// ---- Stage 1 config ----
constexpr int KSPLIT = 8;
constexpr int KRANGE = D_ / KSPLIT;   // 256 k per block
constexpr int S1_THREADS = 256;
constexpr int S1_ROWS = 512;          // 2 rows per thread

// ---- Stage 2 config ----
constexpr int SROWS = 64;
constexpr int S2_THREADS = 256;       // each thread owns 4 d; block covers 1024 d

// Partial h: [split][row][16] -> 16 MB (L2-resident)
constexpr size_t HP_STRIDE = (size_t)B_ * S_ * 16;  // floats per split
__device__ float g_hp[KSPLIT * HP_STRIDE];

// ---- packed f32x2 helpers (sm_100+ PTX) ----
__device__ __forceinline__ unsigned long long fma2(unsigned long long a,
                                                   unsigned long long b,
                                                   unsigned long long c) {
    unsigned long long d;
    asm("fma.rn.f32x2 %0, %1, %2, %3;" : "=l"(d) : "l"(a), "l"(b), "l"(c));
    return d;
}
__device__ __forceinline__ unsigned long long add2(unsigned long long a,
                                                   unsigned long long b) {
    unsigned long long d;
    asm("add.rn.f32x2 %0, %1, %2;" : "=l"(d) : "l"(a), "l"(b));
    return d;
}
__device__ __forceinline__ unsigned long long pack2(float lo, float hi) {
    unsigned long long d;
    asm("mov.b64 %0, {%1, %2};" : "=l"(d) : "f"(lo), "f"(hi));
    return d;
}
__device__ __forceinline__ float2 unpack2(unsigned long long v) {
    float2 r;
    asm("mov.b64 {%0, %1}, %2;" : "=f"(r.x), "=f"(r.y) : "l"(v));
    return r;
}

// ============================================================================
// Stage 1: h_partial[split][row][c] = sum_{k in split range} x[row][k]*Bc[k][c]
// 256 threads, 2 rows/thread (rows tid and tid+256), 16 cols each.
// Whole B k-range (256x16 = 16KB) preloaded to smem once; x streamed from
// gmem in registers. 3 blocks/SM resident -> 24 warps/SM.
// ============================================================================
__global__ __launch_bounds__(S1_THREADS, 3) void lora_stage1(
    const float* __restrict__ x, const float* __restrict__ ab) {
    __shared__ float bs[KRANGE][16];  // 16 KB

    const int tid = threadIdx.x;
    const int row0 = blockIdx.x * S1_ROWS;
    const int split = blockIdx.y;
    const int kbase = split * KRANGE;
    const int b = row0 / S_;

    // Preload B tile: bs[k][j*4+r] = adapter_b[4b+j][kbase+k][r]
    const float* bbase = ab + (size_t)(4 * b) * D_ * R_;
#pragma unroll
    for (int t = tid; t < KRANGE * 4; t += S1_THREADS) {
        const int j = t >> 8;   // t / KRANGE
        const int k = t & 255;  // t % KRANGE -> coalesced
        float4 v = *(const float4*)(bbase + (size_t)j * (D_ * R_) +
                                    (size_t)(kbase + k) * R_);
        *(float4*)&bs[k][j * 4] = v;
    }
    __syncthreads();

    const float* xr0 = x + (size_t)(row0 + tid) * D_ + kbase;
    const float* xr1 = xr0 + (size_t)S1_THREADS * D_;

    unsigned long long acc0[8], acc1[8];
#pragma unroll
    for (int c = 0; c < 8; c++) { acc0[c] = 0ull; acc1[c] = 0ull; }

    // Process 8 k per iteration; prefetch next 8 k.
    float4 xa0 = *(const float4*)(xr0 + 0);
    float4 xa1 = *(const float4*)(xr0 + 4);
    float4 xb0 = *(const float4*)(xr1 + 0);
    float4 xb1 = *(const float4*)(xr1 + 4);

    for (int k0 = 0; k0 < KRANGE; k0 += 8) {
        const int kn = (k0 + 8 < KRANGE) ? (k0 + 8) : k0;  // harmless reload
        float4 na0 = *(const float4*)(xr0 + kn + 0);
        float4 na1 = *(const float4*)(xr0 + kn + 4);
        float4 nb0 = *(const float4*)(xr1 + kn + 0);
        float4 nb1 = *(const float4*)(xr1 + kn + 4);

        float xav[8] = {xa0.x, xa0.y, xa0.z, xa0.w, xa1.x, xa1.y, xa1.z, xa1.w};
        float xbv[8] = {xb0.x, xb0.y, xb0.z, xb0.w, xb1.x, xb1.y, xb1.z, xb1.w};

#pragma unroll
        for (int kk = 0; kk < 8; kk++) {
            const unsigned long long x0 = pack2(xav[kk], xav[kk]);
            const unsigned long long x1 = pack2(xbv[kk], xbv[kk]);
            const ulonglong2* brow = (const ulonglong2*)&bs[k0 + kk][0];
            ulonglong2 bp0 = brow[0];
            ulonglong2 bp1 = brow[1];
            ulonglong2 bp2 = brow[2];
            ulonglong2 bp3 = brow[3];
            acc0[0] = fma2(x0, bp0.x, acc0[0]);
            acc0[1] = fma2(x0, bp0.y, acc0[1]);
            acc0[2] = fma2(x0, bp1.x, acc0[2]);
            acc0[3] = fma2(x0, bp1.y, acc0[3]);
            acc0[4] = fma2(x0, bp2.x, acc0[4]);
            acc0[5] = fma2(x0, bp2.y, acc0[5]);
            acc0[6] = fma2(x0, bp3.x, acc0[6]);
            acc0[7] = fma2(x0, bp3.y, acc0[7]);
            acc1[0] = fma2(x1, bp0.x, acc1[0]);
            acc1[1] = fma2(x1, bp0.y, acc1[1]);
            acc1[2] = fma2(x1, bp1.x, acc1[2]);
            acc1[3] = fma2(x1, bp1.y, acc1[3]);
            acc1[4] = fma2(x1, bp2.x, acc1[4]);
            acc1[5] = fma2(x1, bp2.y, acc1[5]);
            acc1[6] = fma2(x1, bp3.x, acc1[6]);
            acc1[7] = fma2(x1, bp3.y, acc1[7]);
        }
        xa0 = na0; xa1 = na1; xb0 = nb0; xb1 = nb1;
    }

    // Write partial h rows (16 floats each) as 2x STG.128 per row
    float* hp = g_hp + (size_t)split * HP_STRIDE;
    float* o0 = hp + (size_t)(row0 + tid) * 16;
    float* o1 = hp + (size_t)(row0 + tid + S1_THREADS) * 16;
    ((ulonglong2*)o0)[0] = make_ulonglong2(acc0[0], acc0[1]);
    ((ulonglong2*)o0)[1] = make_ulonglong2(acc0[2], acc0[3]);
    ((ulonglong2*)o0)[2] = make_ulonglong2(acc0[4], acc0[5]);
    ((ulonglong2*)o0)[3] = make_ulonglong2(acc0[6], acc0[7]);
    ((ulonglong2*)o1)[0] = make_ulonglong2(acc1[0], acc1[1]);
    ((ulonglong2*)o1)[1] = make_ulonglong2(acc1[2], acc1[3]);
    ((ulonglong2*)o1)[2] = make_ulonglong2(acc1[4], acc1[5]);
    ((ulonglong2*)o1)[3] = make_ulonglong2(acc1[6], acc1[7]);
}

// ============================================================================
// Stage 2: out[row][d] = relu( 0.25 * sum_c h[row][c] * Ac[c][d] )
// 256 threads, each owns 4 consecutive d (A slice in regs); block covers
// 1024 d x 64 rows. hs filled FIRST (before areg is live) to keep register
// pressure <= 85 for 3 blocks/SM.
// ============================================================================
__global__ __launch_bounds__(S2_THREADS, 3) void lora_stage2(
    const float* __restrict__ aa, float* __restrict__ out) {
    __shared__ float2 hs[SROWS][16];  // duplicated (0.25*h, 0.25*h) pairs, 8KB

    const int tid = threadIdx.x;
    const int b = blockIdx.z;
    const int s0 = blockIdx.x * SROWS;
    const size_t row0 = (size_t)b * S_ + s0;
    const int d0 = blockIdx.y * 1024 + tid * 4;

    // Fill hs FIRST: sum 8 partials, scale 0.25, duplicate into pairs.
    {
        const float2* hp = (const float2*)(g_hp) + row0 * 8;
#pragma unroll
        for (int g = 0; g < (SROWS * 8) / S2_THREADS; g++) {
            const int i = tid + g * S2_THREADS;
            float a = 0.0f, c2 = 0.0f;
#pragma unroll
            for (int s = 0; s < KSPLIT; s++) {
                float2 v = hp[(size_t)s * (HP_STRIDE / 2) + i];
                a += v.x;
                c2 += v.y;
            }
            a *= 0.25f;
            c2 *= 0.25f;
            const int rr = i >> 3;
            const int cp = i & 7;
            hs[rr][2 * cp + 0] = make_float2(a, a);
            hs[rr][2 * cp + 1] = make_float2(c2, c2);
        }
    }
    __syncthreads();

    // A slice into registers: 16 c x 4 d -> 16 x 2 f32x2
    unsigned long long areg[16][2];
#pragma unroll
    for (int j = 0; j < 4; j++) {
#pragma unroll
        for (int r = 0; r < 4; r++) {
            float4 v = *(const float4*)(aa + (size_t)(4 * b + j) * (R_ * D_) +
                                        (size_t)r * D_ + d0);
            areg[j * 4 + r][0] = pack2(v.x, v.y);
            areg[j * 4 + r][1] = pack2(v.z, v.w);
        }
    }

    float* orow = out + row0 * D_ + d0;
    for (int rr = 0; rr < SROWS; rr++) {
        unsigned long long a0 = 0ull, a1 = 0ull, a2 = 0ull, a3 = 0ull;
#pragma unroll
        for (int c = 0; c < 16; c += 2) {
            ulonglong2 hv = *(const ulonglong2*)&hs[rr][c];
            a0 = fma2(hv.x, areg[c + 0][0], a0);
            a1 = fma2(hv.x, areg[c + 0][1], a1);
            a2 = fma2(hv.y, areg[c + 1][0], a2);
            a3 = fma2(hv.y, areg[c + 1][1], a3);
        }
        const unsigned long long s01 = add2(a0, a2);
        const unsigned long long s23 = add2(a1, a3);
        float2 v0 = unpack2(s01);
        float2 v1 = unpack2(s23);
        float4 o;
        o.x = fmaxf(v0.x, 0.0f);
        o.y = fmaxf(v0.y, 0.0f);
        o.z = fmaxf(v1.x, 0.0f);
        o.w = fmaxf(v1.y, 0.0f);
        *(float4*)(orow + (size_t)rr * D_) = o;
    }
}

extern "C" void kernel_launch(void* const* d_in, const int* in_sizes, int n_in,
                              void* d_out, int out_size) {
    const float* x = (const float*)d_in[0];
    const float* ab = (const float*)d_in[1];
    const float* aa = (const float*)d_in[2];
    float* out = (float*)d_out;

    dim3 g1((B_ * S_) / S1_ROWS, KSPLIT);  // (64, 8) = 512 blocks
    lora_stage1<<<g1, S1_THREADS>>>(x, ab);

    dim3 g2(S_ / SROWS, D_ / (S2_THREADS * 4), B_);  // (64, 2, 8) = 1024 blocks
    lora_stage2<<<g2, S2_THREADS>>>(aa, out);
}

// round 8
// speedup vs baseline: 1.1140x; 1.1116x over previous
#include <cuda_runtime.h>
#include <cstdint>

// Problem constants (fixed shapes per reference)
constexpr int B_ = 8;
constexpr int S_ = 4096;
constexpr int D_ = 2048;
constexpr int R_ = 4;
// Effective math: out[b,s,:] = relu(0.25 * (x[b,s,:] @ Bc_b) @ Ac_b),
// Bc_b = concat(adapter_b[4b..4b+3]) -> [2048,16], Ac_b -> [16,2048].

// ---- Stage 1 config ----
constexpr int S1_THREADS = 256;
constexpr int S1_ROWS = 128;     // rows per block
constexpr int KSLAB = 64;        // k per smem tile
constexpr int NTILES = D_ / KSLAB;  // 32
constexpr int XS_STR = 65;       // xs row stride (odd -> conflict-free LDS.32)
constexpr int BS_STR = 20;       // bs row stride (mult of 4 -> aligned LDS.128)

// ---- Stage 2 config ----
constexpr int SROWS = 64;
constexpr int S2_THREADS = 256;

// h: [row][16], 2 MB -> L2-resident
__device__ float g_h[(size_t)B_ * S_ * 16];

// ---- packed f32x2 helpers (sm_100+ PTX) ----
__device__ __forceinline__ unsigned long long fma2(unsigned long long a,
                                                   unsigned long long b,
                                                   unsigned long long c) {
    unsigned long long d;
    asm("fma.rn.f32x2 %0, %1, %2, %3;" : "=l"(d) : "l"(a), "l"(b), "l"(c));
    return d;
}
__device__ __forceinline__ unsigned long long add2(unsigned long long a,
                                                   unsigned long long b) {
    unsigned long long d;
    asm("add.rn.f32x2 %0, %1, %2;" : "=l"(d) : "l"(a), "l"(b));
    return d;
}
__device__ __forceinline__ unsigned long long pack2(float lo, float hi) {
    unsigned long long d;
    asm("mov.b64 %0, {%1, %2};" : "=l"(d) : "f"(lo), "f"(hi));
    return d;
}
__device__ __forceinline__ float2 unpack2(unsigned long long v) {
    float2 r;
    asm("mov.b64 {%0, %1}, %2;" : "=f"(r.x), "=f"(r.y) : "l"(v));
    return r;
}

// ============================================================================
// Stage 1: h[row][c] = sum_k x[row][k] * Bc[k][c]
// 256 threads, 128 rows/block, 256 blocks.
// Thread (q = tid>>6, rid = tid&63) owns rows {rid, rid+64} and k-stripe q
// (k_local = q*16 + s within each 64-k slab). All lanes of a warp share the
// same k at each step -> B row reads are pure warp broadcasts (1 wf each).
// x is staged via smem (coalesced LDG; stride-65 conflict-free LDS.32).
// Final 4-way cross-quarter reduction in smem, single h write.
// ============================================================================
__global__ __launch_bounds__(S1_THREADS, 2) void lora_stage1(
    const float* __restrict__ x, const float* __restrict__ ab) {
    __shared__ float xs[S1_ROWS * XS_STR];  // 33.3 KB (reused as reduce buf)
    __shared__ float bs[KSLAB * BS_STR];    // 5.1 KB

    const int tid = threadIdx.x;
    const int q = tid >> 6;    // k-stripe 0..3
    const int rid = tid & 63;  // row slot
    const int row0 = blockIdx.x * S1_ROWS;
    const int b = blockIdx.x >> 5;  // row0 / S_

    const float* bbase = ab + (size_t)(4 * b) * D_ * R_;
    const int bj = tid & 3;         // adapter slot for B loads
    const int bk = tid >> 2;        // k for B loads (0..63)

    unsigned long long acc0[8], acc1[8];
#pragma unroll
    for (int c = 0; c < 8; c++) { acc0[c] = 0ull; acc1[c] = 0ull; }

    // ---- prefetch tile 0 ----
    float4 xv[8];
    float4 bv;
    {
#pragma unroll
        for (int i = 0; i < 8; i++) {
            const int id = tid + i * 256;
            const int r = id >> 4;
            const int k4 = id & 15;
            xv[i] = *(const float4*)(x + (size_t)(row0 + r) * D_ + k4 * 4);
        }
        bv = *(const float4*)(bbase + (size_t)bj * (D_ * R_) + (size_t)bk * R_);
    }

    for (int t = 0; t < NTILES; t++) {
        __syncthreads();  // previous tile's compute done
        // store prefetched tile to smem
#pragma unroll
        for (int i = 0; i < 8; i++) {
            const int id = tid + i * 256;
            const int r = id >> 4;
            const int k4 = id & 15;
            float* p = &xs[r * XS_STR + k4 * 4];
            p[0] = xv[i].x; p[1] = xv[i].y; p[2] = xv[i].z; p[3] = xv[i].w;
        }
        *(float4*)&bs[bk * BS_STR + bj * 4] = bv;
        __syncthreads();

        // prefetch next tile while computing this one
        if (t + 1 < NTILES) {
            const int kb = (t + 1) * KSLAB;
#pragma unroll
            for (int i = 0; i < 8; i++) {
                const int id = tid + i * 256;
                const int r = id >> 4;
                const int k4 = id & 15;
                xv[i] = *(const float4*)(x + (size_t)(row0 + r) * D_ + kb +
                                         k4 * 4);
            }
            bv = *(const float4*)(bbase + (size_t)bj * (D_ * R_) +
                                  (size_t)(kb + bk) * R_);
        }

        // compute my 16-k stripe for 2 rows x 16 cols
        const float* xr0 = &xs[rid * XS_STR + q * 16];
        const float* xr1 = &xs[(rid + 64) * XS_STR + q * 16];
        const ulonglong2* brow0 = (const ulonglong2*)&bs[(q * 16) * BS_STR];
#pragma unroll
        for (int s = 0; s < 16; s++) {
            const float xa = xr0[s];
            const float xb = xr1[s];
            const unsigned long long x0 = pack2(xa, xa);
            const unsigned long long x1 = pack2(xb, xb);
            const ulonglong2* bp =
                (const ulonglong2*)((const float*)brow0 + s * BS_STR);
            ulonglong2 b01 = bp[0];
            ulonglong2 b23 = bp[1];
            acc0[0] = fma2(x0, b01.x, acc0[0]);
            acc0[1] = fma2(x0, b01.y, acc0[1]);
            acc0[2] = fma2(x0, b23.x, acc0[2]);
            acc0[3] = fma2(x0, b23.y, acc0[3]);
            acc1[0] = fma2(x1, b01.x, acc1[0]);
            acc1[1] = fma2(x1, b01.y, acc1[1]);
            acc1[2] = fma2(x1, b23.x, acc1[2]);
            acc1[3] = fma2(x1, b23.y, acc1[3]);
            ulonglong2 b45 = bp[2];
            ulonglong2 b67 = bp[3];
            acc0[4] = fma2(x0, b45.x, acc0[4]);
            acc0[5] = fma2(x0, b45.y, acc0[5]);
            acc0[6] = fma2(x0, b67.x, acc0[6]);
            acc0[7] = fma2(x0, b67.y, acc0[7]);
            acc1[4] = fma2(x1, b45.x, acc1[4]);
            acc1[5] = fma2(x1, b45.y, acc1[5]);
            acc1[6] = fma2(x1, b67.x, acc1[6]);
            acc1[7] = fma2(x1, b67.y, acc1[7]);
        }
    }

    // ---- cross-quarter reduction via smem (reuse xs: need 8192 floats) ----
    __syncthreads();
    float* red = xs;  // red[((q*128 + row)*16 + c)]
    {
        const int base0 = (q * 128 + rid) * 16;
        ulonglong2* p0 = (ulonglong2*)&red[base0];
        p0[0] = make_ulonglong2(acc0[0], acc0[1]);
        p0[1] = make_ulonglong2(acc0[2], acc0[3]);
        p0[2] = make_ulonglong2(acc0[4], acc0[5]);
        p0[3] = make_ulonglong2(acc0[6], acc0[7]);
        const int base1 = (q * 128 + rid + 64) * 16;
        ulonglong2* p1 = (ulonglong2*)&red[base1];
        p1[0] = make_ulonglong2(acc1[0], acc1[1]);
        p1[1] = make_ulonglong2(acc1[2], acc1[3]);
        p1[2] = make_ulonglong2(acc1[4], acc1[5]);
        p1[3] = make_ulonglong2(acc1[6], acc1[7]);
    }
    __syncthreads();

    {
        const int row = tid >> 1;
        const int coff = (tid & 1) * 8;
        float4 sa = make_float4(0.f, 0.f, 0.f, 0.f);
        float4 sb = make_float4(0.f, 0.f, 0.f, 0.f);
#pragma unroll
        for (int qq = 0; qq < 4; qq++) {
            const float* p = &red[(qq * 128 + row) * 16 + coff];
            float4 va = *(const float4*)(p + 0);
            float4 vb = *(const float4*)(p + 4);
            sa.x += va.x; sa.y += va.y; sa.z += va.z; sa.w += va.w;
            sb.x += vb.x; sb.y += vb.y; sb.z += vb.z; sb.w += vb.w;
        }
        float* o = g_h + (size_t)(row0 + row) * 16 + coff;
        *(float4*)(o + 0) = sa;
        *(float4*)(o + 4) = sb;
    }
}

// ============================================================================
// Stage 2: out[row][d] = relu( 0.25 * sum_c h[row][c] * Ac[c][d] )
// 256 threads, each owns 4 consecutive d (A slice in regs); block covers
// 1024 d x 64 rows. Single h stream (2 MB, L2-resident).
// ============================================================================
__global__ __launch_bounds__(S2_THREADS, 3) void lora_stage2(
    const float* __restrict__ aa, float* __restrict__ out) {
    __shared__ float2 hs[SROWS][16];  // duplicated (0.25*h, 0.25*h) pairs, 8KB

    const int tid = threadIdx.x;
    const int b = blockIdx.z;
    const int s0 = blockIdx.x * SROWS;
    const size_t row0 = (size_t)b * S_ + s0;
    const int d0 = blockIdx.y * 1024 + tid * 4;

    // Fill hs FIRST (before areg is live): scale 0.25, duplicate into pairs.
    {
        const float2* hp = (const float2*)g_h + row0 * 8;
#pragma unroll
        for (int g = 0; g < (SROWS * 8) / S2_THREADS; g++) {
            const int i = tid + g * S2_THREADS;
            float2 v = hp[i];
            const float a = v.x * 0.25f;
            const float c2 = v.y * 0.25f;
            const int rr = i >> 3;
            const int cp = i & 7;
            hs[rr][2 * cp + 0] = make_float2(a, a);
            hs[rr][2 * cp + 1] = make_float2(c2, c2);
        }
    }
    __syncthreads();

    // A slice into registers: 16 c x 4 d -> 16 x 2 f32x2
    unsigned long long areg[16][2];
#pragma unroll
    for (int j = 0; j < 4; j++) {
#pragma unroll
        for (int r = 0; r < 4; r++) {
            float4 v = *(const float4*)(aa + (size_t)(4 * b + j) * (R_ * D_) +
                                        (size_t)r * D_ + d0);
            areg[j * 4 + r][0] = pack2(v.x, v.y);
            areg[j * 4 + r][1] = pack2(v.z, v.w);
        }
    }

    float* orow = out + row0 * D_ + d0;
    for (int rr = 0; rr < SROWS; rr++) {
        unsigned long long a0 = 0ull, a1 = 0ull, a2 = 0ull, a3 = 0ull;
#pragma unroll
        for (int c = 0; c < 16; c += 2) {
            ulonglong2 hv = *(const ulonglong2*)&hs[rr][c];
            a0 = fma2(hv.x, areg[c + 0][0], a0);
            a1 = fma2(hv.x, areg[c + 0][1], a1);
            a2 = fma2(hv.y, areg[c + 1][0], a2);
            a3 = fma2(hv.y, areg[c + 1][1], a3);
        }
        const unsigned long long s01 = add2(a0, a2);
        const unsigned long long s23 = add2(a1, a3);
        float2 v0 = unpack2(s01);
        float2 v1 = unpack2(s23);
        float4 o;
        o.x = fmaxf(v0.x, 0.0f);
        o.y = fmaxf(v0.y, 0.0f);
        o.z = fmaxf(v1.x, 0.0f);
        o.w = fmaxf(v1.y, 0.0f);
        *(float4*)(orow + (size_t)rr * D_) = o;
    }
}

extern "C" void kernel_launch(void* const* d_in, const int* in_sizes, int n_in,
                              void* d_out, int out_size) {
    const float* x = (const float*)d_in[0];
    const float* ab = (const float*)d_in[1];
    const float* aa = (const float*)d_in[2];
    float* out = (float*)d_out;

    lora_stage1<<<(B_ * S_) / S1_ROWS, S1_THREADS>>>(x, ab);  // 256 blocks

    dim3 g2(S_ / SROWS, D_ / (S2_THREADS * 4), B_);  // (64, 2, 8) = 1024 blocks
    lora_stage2<<<g2, S2_THREADS>>>(aa, out);
}

// round 9
// speedup vs baseline: 1.4098x; 1.2655x over previous
#include <cuda_runtime.h>
#include <cstdint>

// Problem constants (fixed shapes per reference)
constexpr int B_ = 8;
constexpr int S_ = 4096;
constexpr int D_ = 2048;
constexpr int R_ = 4;
// Effective math: out[b,s,:] = relu(0.25 * (x[b,s,:] @ Bc_b) @ Ac_b),
// Bc_b = concat(adapter_b[4b..4b+3]) -> [2048,16], Ac_b -> [16,2048].

// ---- Stage 1 config ----
constexpr int S1_THREADS = 256;
constexpr int S1_ROWS = 128;        // rows per block
constexpr int KSLAB = 64;           // k per smem tile
constexpr int NTILES = D_ / KSLAB;  // 32
constexpr int XS_STR = 65;          // xs row stride (odd -> conflict-free LDS.32)
constexpr int BS_STR = 20;          // bs row stride (mult of 4 -> aligned LDS.128)

// ---- Stage 2 config ----
constexpr int SROWS = 64;
constexpr int S2_THREADS = 256;

// h: [row][16], 2 MB -> L2-resident
__device__ float g_h[(size_t)B_ * S_ * 16];

// ---- packed f32x2 helpers (sm_100+ PTX) ----
__device__ __forceinline__ unsigned long long fma2(unsigned long long a,
                                                   unsigned long long b,
                                                   unsigned long long c) {
    unsigned long long d;
    asm("fma.rn.f32x2 %0, %1, %2, %3;" : "=l"(d) : "l"(a), "l"(b), "l"(c));
    return d;
}
__device__ __forceinline__ unsigned long long add2(unsigned long long a,
                                                   unsigned long long b) {
    unsigned long long d;
    asm("add.rn.f32x2 %0, %1, %2;" : "=l"(d) : "l"(a), "l"(b));
    return d;
}
__device__ __forceinline__ unsigned long long pack2(float lo, float hi) {
    unsigned long long d;
    asm("mov.b64 %0, {%1, %2};" : "=l"(d) : "f"(lo), "f"(hi));
    return d;
}
__device__ __forceinline__ float2 unpack2(unsigned long long v) {
    float2 r;
    asm("mov.b64 {%0, %1}, %2;" : "=f"(r.x), "=f"(r.y) : "l"(v));
    return r;
}

// ============================================================================
// Stage 1: h[row][c] = sum_k x[row][k] * Bc[k][c]
// 256 threads = q(4 k-stripes) x cg(2 col-halves) x rid(32).
// Thread owns 4 rows {rid,+32,+64,+96} x 8 cols (cg half) x 16-k stripe (q).
// Warp = fixed (q, cg): B reads are warp-broadcast LDS.128, amortized over
// 4 rows (8 wf per 32 fma-cycles). x reads are conflict-free LDS.32.
// Cross-q reduction in smem at the end; single h write.
// ============================================================================
__global__ __launch_bounds__(S1_THREADS, 2) void lora_stage1(
    const float* __restrict__ x, const float* __restrict__ ab) {
    __shared__ float xs[S1_ROWS * XS_STR];  // 33.3 KB (reused as reduce buf)
    __shared__ float bs[KSLAB * BS_STR];    // 5.1 KB

    const int tid = threadIdx.x;
    const int q = tid >> 6;          // k-stripe 0..3
    const int cg = (tid >> 5) & 1;   // col half 0..1
    const int rid = tid & 31;        // row slot within warp
    const int row0 = blockIdx.x * S1_ROWS;
    const int b = blockIdx.x >> 5;   // row0 / S_

    const float* bbase = ab + (size_t)(4 * b) * D_ * R_;
    const int bj = tid & 3;   // adapter slot for B loads
    const int bk = tid >> 2;  // k for B loads (0..63)

    unsigned long long acc[4][4];
#pragma unroll
    for (int rr = 0; rr < 4; rr++)
#pragma unroll
        for (int c = 0; c < 4; c++) acc[rr][c] = 0ull;

    // ---- prefetch tile 0 ----
    float4 xv[8];
    float4 bv;
    {
#pragma unroll
        for (int i = 0; i < 8; i++) {
            const int id = tid + i * 256;
            const int r = id >> 4;
            const int k4 = id & 15;
            xv[i] = *(const float4*)(x + (size_t)(row0 + r) * D_ + k4 * 4);
        }
        bv = *(const float4*)(bbase + (size_t)bj * (D_ * R_) + (size_t)bk * R_);
    }

    for (int t = 0; t < NTILES; t++) {
        __syncthreads();  // previous tile's compute done
        // store prefetched tile to smem
#pragma unroll
        for (int i = 0; i < 8; i++) {
            const int id = tid + i * 256;
            const int r = id >> 4;
            const int k4 = id & 15;
            float* p = &xs[r * XS_STR + k4 * 4];
            p[0] = xv[i].x; p[1] = xv[i].y; p[2] = xv[i].z; p[3] = xv[i].w;
        }
        *(float4*)&bs[bk * BS_STR + bj * 4] = bv;
        __syncthreads();

        // prefetch next tile while computing this one
        if (t + 1 < NTILES) {
            const int kb = (t + 1) * KSLAB;
#pragma unroll
            for (int i = 0; i < 8; i++) {
                const int id = tid + i * 256;
                const int r = id >> 4;
                const int k4 = id & 15;
                xv[i] = *(const float4*)(x + (size_t)(row0 + r) * D_ + kb +
                                         k4 * 4);
            }
            bv = *(const float4*)(bbase + (size_t)bj * (D_ * R_) +
                                  (size_t)(kb + bk) * R_);
        }

        // compute: 16-k stripe, 4 rows, 8 cols
        const float* xr = &xs[rid * XS_STR + q * 16];
        const float* bb = &bs[(q * 16) * BS_STR + cg * 8];
#pragma unroll
        for (int s = 0; s < 16; s++) {
            const float x0 = xr[s];
            const float x1 = xr[32 * XS_STR + s];
            const float x2 = xr[64 * XS_STR + s];
            const float x3 = xr[96 * XS_STR + s];
            const ulonglong2* bp = (const ulonglong2*)(bb + s * BS_STR);
            const ulonglong2 bA = bp[0];  // cols cg*8 .. +3
            const ulonglong2 bB = bp[1];  // cols cg*8+4 .. +7
            const unsigned long long p0 = pack2(x0, x0);
            const unsigned long long p1 = pack2(x1, x1);
            const unsigned long long p2 = pack2(x2, x2);
            const unsigned long long p3 = pack2(x3, x3);
            acc[0][0] = fma2(p0, bA.x, acc[0][0]);
            acc[0][1] = fma2(p0, bA.y, acc[0][1]);
            acc[0][2] = fma2(p0, bB.x, acc[0][2]);
            acc[0][3] = fma2(p0, bB.y, acc[0][3]);
            acc[1][0] = fma2(p1, bA.x, acc[1][0]);
            acc[1][1] = fma2(p1, bA.y, acc[1][1]);
            acc[1][2] = fma2(p1, bB.x, acc[1][2]);
            acc[1][3] = fma2(p1, bB.y, acc[1][3]);
            acc[2][0] = fma2(p2, bA.x, acc[2][0]);
            acc[2][1] = fma2(p2, bA.y, acc[2][1]);
            acc[2][2] = fma2(p2, bB.x, acc[2][2]);
            acc[2][3] = fma2(p2, bB.y, acc[2][3]);
            acc[3][0] = fma2(p3, bA.x, acc[3][0]);
            acc[3][1] = fma2(p3, bA.y, acc[3][1]);
            acc[3][2] = fma2(p3, bB.x, acc[3][2]);
            acc[3][3] = fma2(p3, bB.y, acc[3][3]);
        }
    }

    // ---- cross-q reduction via smem (reuse xs: 4*128*16 = 8192 floats) ----
    __syncthreads();
    float* red = xs;  // red[(q*128 + row)*16 + col]
#pragma unroll
    for (int rr = 0; rr < 4; rr++) {
        const int base = (q * 128 + rid + rr * 32) * 16 + cg * 8;
        ulonglong2* p = (ulonglong2*)&red[base];
        p[0] = make_ulonglong2(acc[rr][0], acc[rr][1]);
        p[1] = make_ulonglong2(acc[rr][2], acc[rr][3]);
    }
    __syncthreads();

    {
        const int row = tid >> 1;
        const int coff = (tid & 1) * 8;
        float4 sa = make_float4(0.f, 0.f, 0.f, 0.f);
        float4 sb = make_float4(0.f, 0.f, 0.f, 0.f);
#pragma unroll
        for (int qq = 0; qq < 4; qq++) {
            const float* p = &red[(qq * 128 + row) * 16 + coff];
            float4 va = *(const float4*)(p + 0);
            float4 vb = *(const float4*)(p + 4);
            sa.x += va.x; sa.y += va.y; sa.z += va.z; sa.w += va.w;
            sb.x += vb.x; sb.y += vb.y; sb.z += vb.z; sb.w += vb.w;
        }
        float* o = g_h + (size_t)(row0 + row) * 16 + coff;
        *(float4*)(o + 0) = sa;
        *(float4*)(o + 4) = sb;
    }
}

// ============================================================================
// Stage 2: out[row][d] = relu( 0.25 * sum_c h[row][c] * Ac[c][d] )
// 256 threads, each owns 4 consecutive d (A slice in regs).
// h read as scalar LDS.32 broadcasts (1 wf each) + pack2 on the ALU pipe --
// cuts crossbar traffic 2x vs LDS.128 pair reads.
// ============================================================================
__global__ __launch_bounds__(S2_THREADS) void lora_stage2(
    const float* __restrict__ aa, float* __restrict__ out) {
    __shared__ float hsf[SROWS * 16];  // 0.25*h scalars, 4KB

    const int tid = threadIdx.x;
    const int b = blockIdx.z;
    const int s0 = blockIdx.x * SROWS;
    const size_t row0 = (size_t)b * S_ + s0;
    const int d0 = blockIdx.y * 1024 + tid * 4;

    // Fill hsf: scale by 0.25
    {
        const float2* hp = (const float2*)g_h + row0 * 8;
#pragma unroll
        for (int g = 0; g < (SROWS * 8) / S2_THREADS; g++) {
            const int i = tid + g * S2_THREADS;
            float2 v = hp[i];
            hsf[2 * i + 0] = v.x * 0.25f;
            hsf[2 * i + 1] = v.y * 0.25f;
        }
    }
    __syncthreads();

    // A slice into registers: 16 c x 4 d -> 16 x 2 f32x2
    unsigned long long areg[16][2];
#pragma unroll
    for (int j = 0; j < 4; j++) {
#pragma unroll
        for (int r = 0; r < 4; r++) {
            float4 v = *(const float4*)(aa + (size_t)(4 * b + j) * (R_ * D_) +
                                        (size_t)r * D_ + d0);
            areg[j * 4 + r][0] = pack2(v.x, v.y);
            areg[j * 4 + r][1] = pack2(v.z, v.w);
        }
    }

    float* orow = out + row0 * D_ + d0;
    for (int rr = 0; rr < SROWS; rr++) {
        const float* hrow = &hsf[rr * 16];
        unsigned long long a0 = 0ull, a1 = 0ull, a2 = 0ull, a3 = 0ull;
#pragma unroll
        for (int c = 0; c < 16; c += 2) {
            const float h0 = hrow[c];
            const float h1 = hrow[c + 1];
            const unsigned long long hp0 = pack2(h0, h0);
            const unsigned long long hp1 = pack2(h1, h1);
            a0 = fma2(hp0, areg[c + 0][0], a0);
            a1 = fma2(hp0, areg[c + 0][1], a1);
            a2 = fma2(hp1, areg[c + 1][0], a2);
            a3 = fma2(hp1, areg[c + 1][1], a3);
        }
        const unsigned long long s01 = add2(a0, a2);
        const unsigned long long s23 = add2(a1, a3);
        float2 v0 = unpack2(s01);
        float2 v1 = unpack2(s23);
        float4 o;
        o.x = fmaxf(v0.x, 0.0f);
        o.y = fmaxf(v0.y, 0.0f);
        o.z = fmaxf(v1.x, 0.0f);
        o.w = fmaxf(v1.y, 0.0f);
        *(float4*)(orow + (size_t)rr * D_) = o;
    }
}

extern "C" void kernel_launch(void* const* d_in, const int* in_sizes, int n_in,
                              void* d_out, int out_size) {
    const float* x = (const float*)d_in[0];
    const float* ab = (const float*)d_in[1];
    const float* aa = (const float*)d_in[2];
    float* out = (float*)d_out;

    lora_stage1<<<(B_ * S_) / S1_ROWS, S1_THREADS>>>(x, ab);  // 256 blocks

    dim3 g2(S_ / SROWS, D_ / (S2_THREADS * 4), B_);  // (64, 2, 8) = 1024 blocks
    lora_stage2<<<g2, S2_THREADS>>>(aa, out);
}